// round 3
// baseline (speedup 1.0000x reference)
#include <cuda_runtime.h>

#define Bq      8
#define CIN     2
#define BINS    1024
#define FRAMES  512
#define Cc      8
#define Ee      1024
#define NTOT    (Bq * FRAMES)      // 4096 vectors per codebook channel

// ---------------- scratch (device globals: no allocation allowed) ----------
__device__ __align__(256) float g_v[(size_t)Cc * NTOT * BINS];   // v[c][n][bin]
__device__ __align__(256) float g_e2[Cc * Ee];
__device__ __align__(256) unsigned long long g_arg[Cc * NTOT];   // packed (score,idx)
__device__ float g_loss;

// ---------------- init: reset argmin keys + loss ---------------------------
__global__ void init_k() {
    int i = blockIdx.x * blockDim.x + threadIdx.x;
    if (i < Cc * NTOT) g_arg[i] = 0xFFFFFFFFFFFFFFFFULL;
    if (i == 0) g_loss = 0.0f;
}

// ---------------- fused conv1 -> leaky -> conv2 + skip -> v ----------------
#define BT 16   // bin tile
#define FT 32   // frame tile

__global__ __launch_bounds__(256) void conv_k(
    const float* __restrict__ x,
    const float* __restrict__ w1, const float* __restrict__ b1,
    const float* __restrict__ w2, const float* __restrict__ b2,
    const float* __restrict__ ws, const float* __restrict__ bs)
{
    __shared__ float xs[CIN][BT + 16][FT + 1];   // halo 8 each side
    __shared__ float h1s[Cc][BT + 8][FT + 1];    // halo 4 each side
    __shared__ float w1s[Cc * CIN * 9];
    __shared__ float w2s[Cc * Cc * 9];
    __shared__ float wss[Cc * CIN];
    __shared__ float b1sh[Cc], b2sh[Cc], bssh[Cc];

    const int t    = threadIdx.x;
    const int bin0 = blockIdx.x * BT;
    const int f0   = blockIdx.y * FT;
    const int b    = blockIdx.z;

    for (int i = t; i < Cc * CIN * 9; i += 256) w1s[i] = w1[i];
    for (int i = t; i < Cc * Cc * 9;  i += 256) w2s[i] = w2[i];
    if (t < Cc * CIN) wss[t] = ws[t];
    if (t < Cc) { b1sh[t] = b1[t]; b2sh[t] = b2[t]; bssh[t] = bs[t]; }

    // load x tile with halo 8
    for (int p = t; p < CIN * (BT + 16) * FT; p += 256) {
        int f  = p % FT;
        int rb = (p / FT) % (BT + 16);
        int ci = p / (FT * (BT + 16));
        int gb = bin0 - 8 + rb;
        float v = 0.0f;
        if (gb >= 0 && gb < BINS)
            v = x[((size_t)(b * CIN + ci) * BINS + gb) * FRAMES + f0 + f];
        xs[ci][rb][f] = v;
    }
    __syncthreads();

    // h1 (with halo 4), leaky-relu, zero outside valid bin range (conv2 padding)
    for (int p = t; p < (BT + 8) * FT; p += 256) {
        int f  = p % FT;
        int rb = p / FT;                 // 0..BT+7
        int gb = bin0 - 4 + rb;
        float acc[Cc];
#pragma unroll
        for (int c = 0; c < Cc; c++) acc[c] = b1sh[c];
#pragma unroll
        for (int ci = 0; ci < CIN; ci++)
#pragma unroll
            for (int k = 0; k < 9; k++) {
                float xv = xs[ci][rb + k][f];
#pragma unroll
                for (int c = 0; c < Cc; c++)
                    acc[c] += xv * w1s[(c * CIN + ci) * 9 + k];
            }
#pragma unroll
        for (int c = 0; c < Cc; c++) {
            float h = acc[c];
            h = (h >= 0.0f) ? h : 0.2f * h;
            if (gb < 0 || gb >= BINS) h = 0.0f;
            h1s[c][rb][f] = h;
        }
    }
    __syncthreads();

    // h2 = conv2(h1) + skip(x) ; write v[c][n][bin] (coalesced along bin)
    const int binL = t % BT;     // 0..15
    const int fL0  = t / BT;     // 0..15  (two frame slices per thread)
    float acc[2][Cc];
#pragma unroll
    for (int i = 0; i < 2; i++)
#pragma unroll
        for (int c = 0; c < Cc; c++) acc[i][c] = b2sh[c] + bssh[c];

#pragma unroll
    for (int c2 = 0; c2 < Cc; c2++)
#pragma unroll
        for (int k = 0; k < 9; k++) {
            float w[Cc];
#pragma unroll
            for (int c = 0; c < Cc; c++) w[c] = w2s[(c * Cc + c2) * 9 + k];
#pragma unroll
            for (int i = 0; i < 2; i++) {
                float hv = h1s[c2][binL + k][fL0 + 16 * i];
#pragma unroll
                for (int c = 0; c < Cc; c++) acc[i][c] += hv * w[c];
            }
        }
#pragma unroll
    for (int ci = 0; ci < CIN; ci++)
#pragma unroll
        for (int i = 0; i < 2; i++) {
            float xv = xs[ci][binL + 8][fL0 + 16 * i];
#pragma unroll
            for (int c = 0; c < Cc; c++) acc[i][c] += xv * wss[c * CIN + ci];
        }

    const int gb = bin0 + binL;
#pragma unroll
    for (int i = 0; i < 2; i++) {
        int n = b * FRAMES + f0 + fL0 + 16 * i;
#pragma unroll
        for (int c = 0; c < Cc; c++)
            g_v[((size_t)c * NTOT + n) * BINS + gb] = acc[i][c];
    }
}

// ---------------- e2 = ||codebook row||^2 ----------------------------------
__global__ void e2_k(const float* __restrict__ cb) {
    int warp = threadIdx.x >> 5, lane = threadIdx.x & 31;
    int row  = blockIdx.x * 8 + warp;              // 0..8191
    const float* p = cb + (size_t)row * BINS;
    float s = 0.0f;
    for (int j = lane; j < BINS; j += 32) { float v = p[j]; s += v * v; }
#pragma unroll
    for (int o = 16; o; o >>= 1) s += __shfl_down_sync(0xffffffffu, s, o);
    if (lane == 0) g_e2[row] = s;
}

// ---------------- GEMM (v . cb^T) + argmin(e2 - 2 dot) ---------------------
// 128x128 block tile, 8x8 per thread, TK=8, double-buffered smem.
#define BM  128
#define BE  128
#define BKk 8

__device__ __forceinline__ unsigned orderF(float f) {
    unsigned u = __float_as_uint(f);
    return (u & 0x80000000u) ? ~u : (u | 0x80000000u);
}

__global__ __launch_bounds__(256) void gemm_argmin_k(const float* __restrict__ cb) {
    // gemm buffers: As[2][8][128] (4KB*2) + Bs[2][8][128] (4KB*2) = 16KB
    // epilogue reuse: u64 red[128][17] = 17408 B  -> take max
    __shared__ __align__(16) unsigned char smem_raw[128 * 17 * 8];
    float (*As)[BKk][BM] = (float (*)[BKk][BM])smem_raw;
    float (*Bs)[BKk][BE] = (float (*)[BKk][BE])(smem_raw + 8192);

    const int t     = threadIdx.x;
    const int c     = blockIdx.z;
    const int eBase = blockIdx.x * BE;
    const int mBase = blockIdx.y * BM;
    const float* A  = g_v + (size_t)c * NTOT * BINS + (size_t)mBase * BINS;
    const float* Bm = cb  + (size_t)c * Ee * BINS  + (size_t)eBase * BINS;

    const int lrow = t >> 1;         // 0..127
    const int lk   = (t & 1) * 4;    // 0 or 4
    const int tx   = t % 16;         // e-tile position
    const int ty   = t / 16;         // m-tile position

    float acc[8][8];
#pragma unroll
    for (int i = 0; i < 8; i++)
#pragma unroll
        for (int j = 0; j < 8; j++) acc[i][j] = 0.0f;

    // prologue: load k-slab 0 into buffer 0
    {
        float4 a4 = *(const float4*)&A [(size_t)lrow * BINS + lk];
        float4 b4 = *(const float4*)&Bm[(size_t)lrow * BINS + lk];
        As[0][lk + 0][lrow] = a4.x; As[0][lk + 1][lrow] = a4.y;
        As[0][lk + 2][lrow] = a4.z; As[0][lk + 3][lrow] = a4.w;
        Bs[0][lk + 0][lrow] = b4.x; Bs[0][lk + 1][lrow] = b4.y;
        Bs[0][lk + 2][lrow] = b4.z; Bs[0][lk + 3][lrow] = b4.w;
    }
    __syncthreads();

    for (int k0 = 0; k0 < BINS; k0 += BKk) {
        const int buf  = (k0 >> 3) & 1;
        const bool more = (k0 + BKk) < BINS;
        float4 na, nb;
        if (more) {
            na = *(const float4*)&A [(size_t)lrow * BINS + k0 + BKk + lk];
            nb = *(const float4*)&Bm[(size_t)lrow * BINS + k0 + BKk + lk];
        }
#pragma unroll
        for (int k = 0; k < BKk; k++) {
            float av[8], bv[8];
            *(float4*)&av[0] = *(const float4*)&As[buf][k][ty * 4];
            *(float4*)&av[4] = *(const float4*)&As[buf][k][64 + ty * 4];
            *(float4*)&bv[0] = *(const float4*)&Bs[buf][k][tx * 4];
            *(float4*)&bv[4] = *(const float4*)&Bs[buf][k][64 + tx * 4];
#pragma unroll
            for (int i = 0; i < 8; i++)
#pragma unroll
                for (int j = 0; j < 8; j++) acc[i][j] += av[i] * bv[j];
        }
        if (more) {
            const int nbuf = buf ^ 1;
            As[nbuf][lk + 0][lrow] = na.x; As[nbuf][lk + 1][lrow] = na.y;
            As[nbuf][lk + 2][lrow] = na.z; As[nbuf][lk + 3][lrow] = na.w;
            Bs[nbuf][lk + 0][lrow] = nb.x; Bs[nbuf][lk + 1][lrow] = nb.y;
            Bs[nbuf][lk + 2][lrow] = nb.z; Bs[nbuf][lk + 3][lrow] = nb.w;
        }
        __syncthreads();
    }

    // ---- epilogue: score = e2 - 2*dot ; per-row argmin ----
    float e2loc[8];
#pragma unroll
    for (int j = 0; j < 4; j++) {
        e2loc[j]     = g_e2[c * Ee + eBase + tx * 4 + j];
        e2loc[4 + j] = g_e2[c * Ee + eBase + 64 + tx * 4 + j];
    }

    typedef unsigned long long u64;
    u64 (*red)[17] = (u64 (*)[17])smem_raw;   // [128][17] padded vs bank conflicts

#pragma unroll
    for (int rg = 0; rg < 2; rg++)
#pragma unroll
        for (int i = 0; i < 4; i++) {
            const int rowL = rg * 64 + ty * 4 + i;
            float bestv = 3.4e38f; int beste = 0;
#pragma unroll
            for (int jg = 0; jg < 2; jg++)
#pragma unroll
                for (int j = 0; j < 4; j++) {
                    float s = e2loc[jg * 4 + j] - 2.0f * acc[rg * 4 + i][jg * 4 + j];
                    int   e = eBase + jg * 64 + tx * 4 + j;
                    if (s < bestv) { bestv = s; beste = e; }
                }
            red[rowL][tx] = ((u64)orderF(bestv) << 32) | (unsigned)beste;
        }
    __syncthreads();
    if (t < 128) {
        u64 best = red[t][0];
#pragma unroll
        for (int j = 1; j < 16; j++) {
            u64 v = red[t][j];
            if (v < best) best = v;
        }
        atomicMin(&g_arg[c * NTOT + mBase + t], best);
    }
}

// ---------------- gather + transpose + channel-reverse + loss --------------
__global__ __launch_bounds__(256) void gather_k(const float* __restrict__ cb,
                                                float* __restrict__ out)
{
    __shared__ float qs[32][33];
    __shared__ int   idxs[32];
    __shared__ float rsum[256];

    const int t    = threadIdx.x;
    const int c    = blockIdx.z;
    const int n0   = blockIdx.y * 32;
    const int bin0 = blockIdx.x * 32;

    if (t < 32) idxs[t] = (int)(g_arg[c * NTOT + n0 + t] & 0xFFFFFFFFULL);
    __syncthreads();

    // read phase: bin-fast (coalesced cb + v reads)
    {
        int binL = t % 32, fL0 = t / 32;
        float lacc = 0.0f;
#pragma unroll
        for (int i = 0; i < 4; i++) {
            int fL = fL0 + 8 * i;
            int n  = n0 + fL;
            float qv = cb[((size_t)c * Ee + idxs[fL]) * BINS + bin0 + binL];
            float vv = g_v[((size_t)c * NTOT + n) * BINS + bin0 + binL];
            float d = qv - vv;
            lacc += d * d;
            qs[fL][binL] = qv;
        }
        rsum[t] = lacc;
    }
    __syncthreads();

    // write phase: frame-fast (coalesced output), channel reversed
    {
        int fL = t % 32, bL0 = t / 32;
        int b = n0 / FRAMES, fbase = n0 % FRAMES;
        int cOut = (Cc - 1) - c;
#pragma unroll
        for (int i = 0; i < 4; i++) {
            int bL = bL0 + 8 * i;
            out[(((size_t)b * Cc + cOut) * BINS + bin0 + bL) * FRAMES + fbase + fL]
                = qs[fL][bL];
        }
    }
    // loss block-reduce
    __syncthreads();
    for (int s2 = 128; s2; s2 >>= 1) {
        if (t < s2) rsum[t] += rsum[t + s2];
        __syncthreads();
    }
    if (t == 0) atomicAdd(&g_loss, rsum[0]);
}

// ---------------- finalize loss --------------------------------------------
__global__ void fin_k(float* __restrict__ out, int lossIdx) {
    if (threadIdx.x == 0)
        out[lossIdx] = 1.25f * g_loss / (float)((size_t)NTOT * BINS);
}

// ---------------- launch ----------------------------------------------------
extern "C" void kernel_launch(void* const* d_in, const int* in_sizes, int n_in,
                              void* d_out, int out_size)
{
    const float* x  = (const float*)d_in[0];
    const float* w1 = (const float*)d_in[1];
    const float* b1 = (const float*)d_in[2];
    const float* w2 = (const float*)d_in[3];
    const float* b2 = (const float*)d_in[4];
    const float* ws = (const float*)d_in[5];
    const float* bs = (const float*)d_in[6];
    const float* cb = (const float*)d_in[7];
    float* out = (float*)d_out;

    init_k<<<((Cc * NTOT) + 255) / 256, 256>>>();
    conv_k<<<dim3(BINS / BT, FRAMES / FT, Bq), 256>>>(x, w1, b1, w2, b2, ws, bs);
    e2_k<<<(Cc * Ee) / 8, 256>>>(cb);
    gemm_argmin_k<<<dim3(Ee / BE, NTOT / BM, Cc), 256>>>(cb);
    gather_k<<<dim3(BINS / 32, NTOT / 32, Cc), 256>>>(cb, out);
    fin_k<<<1, 32>>>(out, out_size - 1);
}

// round 4
// speedup vs baseline: 1.1239x; 1.1239x over previous
#include <cuda_runtime.h>
#include <cstdint>

#define Bq      8
#define CIN     2
#define BINS    1024
#define FRAMES  512
#define Cc      8
#define Ee      1024
#define NTOT    (Bq * FRAMES)      // 4096 vectors per codebook channel

// ---------------- scratch (device globals: no allocation allowed) ----------
__device__ __align__(256) float g_v [(size_t)Cc * NTOT * BINS];  // v[c][n][bin]
__device__ __align__(256) float g_vh[(size_t)Cc * NTOT * BINS];  // tf32 hi
__device__ __align__(256) float g_vl[(size_t)Cc * NTOT * BINS];  // tf32 lo
__device__ __align__(256) float g_cbh[(size_t)Cc * Ee * BINS];
__device__ __align__(256) float g_cbl[(size_t)Cc * Ee * BINS];
__device__ __align__(256) float g_e2[Cc * Ee];
__device__ __align__(256) unsigned long long g_arg[Cc * NTOT];   // packed (score,idx)
__device__ float g_loss;

__device__ __forceinline__ void tf32split(float x, float& hi, float& lo) {
    uint32_t h;
    asm("cvt.rna.tf32.f32 %0, %1;" : "=r"(h) : "f"(x));
    hi = __uint_as_float(h);
    float r = x - hi;
    uint32_t l;
    asm("cvt.rna.tf32.f32 %0, %1;" : "=r"(l) : "f"(r));
    lo = __uint_as_float(l);
}

// ---------------- init: reset argmin keys + loss ---------------------------
__global__ void init_k() {
    int i = blockIdx.x * blockDim.x + threadIdx.x;
    if (i < Cc * NTOT) g_arg[i] = 0xFFFFFFFFFFFFFFFFULL;
    if (i == 0) g_loss = 0.0f;
}

// ---------------- fused conv1 -> leaky -> conv2 + skip -> v (+hi/lo) -------
#define BT 16   // bin tile
#define FT 32   // frame tile

__global__ __launch_bounds__(256) void conv_k(
    const float* __restrict__ x,
    const float* __restrict__ w1, const float* __restrict__ b1,
    const float* __restrict__ w2, const float* __restrict__ b2,
    const float* __restrict__ ws, const float* __restrict__ bs)
{
    __shared__ float xs[CIN][BT + 16][FT + 1];   // halo 8 each side
    __shared__ float h1s[Cc][BT + 8][FT + 1];    // halo 4 each side
    __shared__ float w1s[Cc * CIN * 9];
    __shared__ float w2s[Cc * Cc * 9];
    __shared__ float wss[Cc * CIN];
    __shared__ float b1sh[Cc], b2sh[Cc], bssh[Cc];

    const int t    = threadIdx.x;
    const int bin0 = blockIdx.x * BT;
    const int f0   = blockIdx.y * FT;
    const int b    = blockIdx.z;

    for (int i = t; i < Cc * CIN * 9; i += 256) w1s[i] = w1[i];
    for (int i = t; i < Cc * Cc * 9;  i += 256) w2s[i] = w2[i];
    if (t < Cc * CIN) wss[t] = ws[t];
    if (t < Cc) { b1sh[t] = b1[t]; b2sh[t] = b2[t]; bssh[t] = bs[t]; }

    for (int p = t; p < CIN * (BT + 16) * FT; p += 256) {
        int f  = p % FT;
        int rb = (p / FT) % (BT + 16);
        int ci = p / (FT * (BT + 16));
        int gb = bin0 - 8 + rb;
        float v = 0.0f;
        if (gb >= 0 && gb < BINS)
            v = x[((size_t)(b * CIN + ci) * BINS + gb) * FRAMES + f0 + f];
        xs[ci][rb][f] = v;
    }
    __syncthreads();

    for (int p = t; p < (BT + 8) * FT; p += 256) {
        int f  = p % FT;
        int rb = p / FT;
        int gb = bin0 - 4 + rb;
        float acc[Cc];
#pragma unroll
        for (int c = 0; c < Cc; c++) acc[c] = b1sh[c];
#pragma unroll
        for (int ci = 0; ci < CIN; ci++)
#pragma unroll
            for (int k = 0; k < 9; k++) {
                float xv = xs[ci][rb + k][f];
#pragma unroll
                for (int c = 0; c < Cc; c++)
                    acc[c] += xv * w1s[(c * CIN + ci) * 9 + k];
            }
#pragma unroll
        for (int c = 0; c < Cc; c++) {
            float h = acc[c];
            h = (h >= 0.0f) ? h : 0.2f * h;
            if (gb < 0 || gb >= BINS) h = 0.0f;
            h1s[c][rb][f] = h;
        }
    }
    __syncthreads();

    const int binL = t % BT;
    const int fL0  = t / BT;
    float acc[2][Cc];
#pragma unroll
    for (int i = 0; i < 2; i++)
#pragma unroll
        for (int c = 0; c < Cc; c++) acc[i][c] = b2sh[c] + bssh[c];

#pragma unroll
    for (int c2 = 0; c2 < Cc; c2++)
#pragma unroll
        for (int k = 0; k < 9; k++) {
            float w[Cc];
#pragma unroll
            for (int c = 0; c < Cc; c++) w[c] = w2s[(c * Cc + c2) * 9 + k];
#pragma unroll
            for (int i = 0; i < 2; i++) {
                float hv = h1s[c2][binL + k][fL0 + 16 * i];
#pragma unroll
                for (int c = 0; c < Cc; c++) acc[i][c] += hv * w[c];
            }
        }
#pragma unroll
    for (int ci = 0; ci < CIN; ci++)
#pragma unroll
        for (int i = 0; i < 2; i++) {
            float xv = xs[ci][binL + 8][fL0 + 16 * i];
#pragma unroll
            for (int c = 0; c < Cc; c++) acc[i][c] += xv * wss[c * CIN + ci];
        }

    const int gb = bin0 + binL;
#pragma unroll
    for (int i = 0; i < 2; i++) {
        int n = b * FRAMES + f0 + fL0 + 16 * i;
#pragma unroll
        for (int c = 0; c < Cc; c++) {
            size_t idx = ((size_t)c * NTOT + n) * BINS + gb;
            float vv = acc[i][c];
            float hi, lo; tf32split(vv, hi, lo);
            g_v[idx]  = vv;
            g_vh[idx] = hi;
            g_vl[idx] = lo;
        }
    }
}

// ---------------- e2 = ||codebook row||^2 ; also write tf32 hi/lo ----------
__global__ void e2_k(const float* __restrict__ cb) {
    int warp = threadIdx.x >> 5, lane = threadIdx.x & 31;
    int row  = blockIdx.x * 8 + warp;              // 0..8191
    const size_t base = (size_t)row * BINS;
    float s = 0.0f;
    for (int j = lane; j < BINS; j += 32) {
        float v = cb[base + j];
        s += v * v;
        float hi, lo; tf32split(v, hi, lo);
        g_cbh[base + j] = hi;
        g_cbl[base + j] = lo;
    }
#pragma unroll
    for (int o = 16; o; o >>= 1) s += __shfl_down_sync(0xffffffffu, s, o);
    if (lane == 0) g_e2[row] = s;
}

// ---------------- tensor-core GEMM (tf32 x3) + argmin ----------------------
// 128x128 block tile, 8 warps (2m x 4n) of 64x32, BK=16 double-buffered via
// cp.async. 3-pass compensated tf32: hi*hi + hi*lo + lo*hi, fp32 accumulate.
#define BM   128
#define BE   128
#define BKs  16
#define STR  20              // smem row stride (floats), conflict-free
#define TILE_F (128 * STR)   // 2560 floats per tile
#define BUF_F  (4 * TILE_F)  // 10240 floats per buffer (Ah,Al,Bh,Bl)
#define GEMM_SMEM_BYTES (2 * BUF_F * 4)   // 81920

__device__ __forceinline__ unsigned orderF(float f) {
    unsigned u = __float_as_uint(f);
    return (u & 0x80000000u) ? ~u : (u | 0x80000000u);
}

__device__ __forceinline__ void cp16(uint32_t dst, const float* src) {
    asm volatile("cp.async.cg.shared.global [%0], [%1], 16;" :: "r"(dst), "l"(src));
}

#define MMA_TF32(d, a, b) \
    asm volatile("mma.sync.aligned.m16n8k8.row.col.f32.tf32.tf32.f32 " \
                 "{%0,%1,%2,%3}, {%4,%5,%6,%7}, {%8,%9}, {%0,%1,%2,%3};" \
                 : "+f"(d[0]), "+f"(d[1]), "+f"(d[2]), "+f"(d[3]) \
                 : "r"(a[0]), "r"(a[1]), "r"(a[2]), "r"(a[3]), \
                   "r"(b[0]), "r"(b[1]))

__global__ __launch_bounds__(256, 2) void gemm_argmin_k() {
    extern __shared__ float S[];
    const int t    = threadIdx.x;
    const int lane = t & 31;
    const int w    = t >> 5;
    const int mw   = w >> 2;          // 0..1
    const int nw   = w & 3;           // 0..3
    const int m_base = mw * 64;
    const int n_base = nw * 32;

    const int c     = blockIdx.z;
    const int eBase = blockIdx.x * BE;
    const int mBase = blockIdx.y * BM;

    const float* srcs[4] = {
        g_vh  + (size_t)c * NTOT * BINS + (size_t)mBase * BINS,
        g_vl  + (size_t)c * NTOT * BINS + (size_t)mBase * BINS,
        g_cbh + (size_t)c * Ee   * BINS + (size_t)eBase * BINS,
        g_cbl + (size_t)c * Ee   * BINS + (size_t)eBase * BINS
    };

    const uint32_t sbase = (uint32_t)__cvta_generic_to_shared(S);
    const int lrow = t >> 1;               // 0..127  (for 2-float4-per-row scheme)
    (void)lrow;

    // loader: per matrix, 2 float4 per thread (512 float4 positions)
    auto load_slab = [&](int k0, int buf) {
#pragma unroll
        for (int m = 0; m < 4; m++) {
            const float* src = srcs[m];
#pragma unroll
            for (int i = 0; i < 2; i++) {
                int id  = t + 256 * i;
                int row = id >> 2;
                int kq  = (id & 3) * 4;
                cp16(sbase + (uint32_t)((buf * BUF_F + m * TILE_F + row * STR + kq) * 4),
                     src + (size_t)row * BINS + k0 + kq);
            }
        }
        asm volatile("cp.async.commit_group;");
    };

    float acc[4][4][4];
#pragma unroll
    for (int mi = 0; mi < 4; mi++)
#pragma unroll
        for (int ni = 0; ni < 4; ni++)
#pragma unroll
            for (int r = 0; r < 4; r++) acc[mi][ni][r] = 0.0f;

    load_slab(0, 0);

    const int r4 = lane >> 2;     // 0..7
    const int c4 = lane & 3;      // 0..3

    for (int s = 0; s < BINS / BKs; s++) {
        const int buf = s & 1;
        asm volatile("cp.async.wait_group 0;");
        __syncthreads();
        if (s + 1 < BINS / BKs) load_slab((s + 1) * BKs, buf ^ 1);

        const float* Ah = S + buf * BUF_F;
        const float* Al = Ah + TILE_F;
        const float* Bh = Ah + 2 * TILE_F;
        const float* Bl = Ah + 3 * TILE_F;

#pragma unroll
        for (int ks = 0; ks < BKs; ks += 8) {
            uint32_t aH[4][4], bH[4][2];
#pragma unroll
            for (int mi = 0; mi < 4; mi++) {
                int o = (m_base + mi * 16 + r4) * STR + ks + c4;
                aH[mi][0] = __float_as_uint(Ah[o]);
                aH[mi][1] = __float_as_uint(Ah[o + 8 * STR]);
                aH[mi][2] = __float_as_uint(Ah[o + 4]);
                aH[mi][3] = __float_as_uint(Ah[o + 8 * STR + 4]);
            }
#pragma unroll
            for (int ni = 0; ni < 4; ni++) {
                int o = (n_base + ni * 8 + r4) * STR + ks + c4;
                bH[ni][0] = __float_as_uint(Bh[o]);
                bH[ni][1] = __float_as_uint(Bh[o + 4]);
            }
            // pass 1: hi * hi
#pragma unroll
            for (int mi = 0; mi < 4; mi++)
#pragma unroll
                for (int ni = 0; ni < 4; ni++)
                    MMA_TF32(acc[mi][ni], aH[mi], bH[ni]);
            // pass 2: hi * lo
            {
                uint32_t bL[4][2];
#pragma unroll
                for (int ni = 0; ni < 4; ni++) {
                    int o = (n_base + ni * 8 + r4) * STR + ks + c4;
                    bL[ni][0] = __float_as_uint(Bl[o]);
                    bL[ni][1] = __float_as_uint(Bl[o + 4]);
                }
#pragma unroll
                for (int mi = 0; mi < 4; mi++)
#pragma unroll
                    for (int ni = 0; ni < 4; ni++)
                        MMA_TF32(acc[mi][ni], aH[mi], bL[ni]);
            }
            // pass 3: lo * hi
            {
                uint32_t aL[4][4];
#pragma unroll
                for (int mi = 0; mi < 4; mi++) {
                    int o = (m_base + mi * 16 + r4) * STR + ks + c4;
                    aL[mi][0] = __float_as_uint(Al[o]);
                    aL[mi][1] = __float_as_uint(Al[o + 8 * STR]);
                    aL[mi][2] = __float_as_uint(Al[o + 4]);
                    aL[mi][3] = __float_as_uint(Al[o + 8 * STR + 4]);
                }
#pragma unroll
                for (int mi = 0; mi < 4; mi++)
#pragma unroll
                    for (int ni = 0; ni < 4; ni++)
                        MMA_TF32(acc[mi][ni], aL[mi], bH[ni]);
            }
        }
        __syncthreads();
    }

    // ---- epilogue: score = e2 - 2*dot ; per-row argmin ----
    typedef unsigned long long u64;
    u64 (*red)[17] = (u64 (*)[17])S;   // 128 x 17 padded

#pragma unroll
    for (int mi = 0; mi < 4; mi++)
#pragma unroll
        for (int h = 0; h < 2; h++) {
            int rowL = m_base + mi * 16 + r4 + h * 8;
            float best = 3.4e38f; int be = 0;
#pragma unroll
            for (int ni = 0; ni < 4; ni++)
#pragma unroll
                for (int j = 0; j < 2; j++) {
                    int col = n_base + ni * 8 + c4 * 2 + j;
                    float sc = g_e2[c * Ee + eBase + col]
                             - 2.0f * acc[mi][ni][h * 2 + j];
                    if (sc < best) { best = sc; be = eBase + col; }
                }
            red[rowL][nw * 4 + c4] =
                ((u64)orderF(best) << 32) | (unsigned)be;
        }
    __syncthreads();
    if (t < 128) {
        u64 best = red[t][0];
#pragma unroll
        for (int j = 1; j < 16; j++) {
            u64 v = red[t][j];
            if (v < best) best = v;
        }
        atomicMin(&g_arg[c * NTOT + mBase + t], best);
    }
}

// ---------------- gather + transpose + channel-reverse + loss --------------
__global__ __launch_bounds__(256) void gather_k(const float* __restrict__ cb,
                                                float* __restrict__ out)
{
    __shared__ float qs[32][33];
    __shared__ int   idxs[32];
    __shared__ float rsum[256];

    const int t    = threadIdx.x;
    const int c    = blockIdx.z;
    const int n0   = blockIdx.y * 32;
    const int bin0 = blockIdx.x * 32;

    if (t < 32) idxs[t] = (int)(g_arg[c * NTOT + n0 + t] & 0xFFFFFFFFULL);
    __syncthreads();

    {
        int binL = t % 32, fL0 = t / 32;
        float lacc = 0.0f;
#pragma unroll
        for (int i = 0; i < 4; i++) {
            int fL = fL0 + 8 * i;
            int n  = n0 + fL;
            float qv = cb[((size_t)c * Ee + idxs[fL]) * BINS + bin0 + binL];
            float vv = g_v[((size_t)c * NTOT + n) * BINS + bin0 + binL];
            float d = qv - vv;
            lacc += d * d;
            qs[fL][binL] = qv;
        }
        rsum[t] = lacc;
    }
    __syncthreads();

    {
        int fL = t % 32, bL0 = t / 32;
        int b = n0 / FRAMES, fbase = n0 % FRAMES;
        int cOut = (Cc - 1) - c;
#pragma unroll
        for (int i = 0; i < 4; i++) {
            int bL = bL0 + 8 * i;
            out[(((size_t)b * Cc + cOut) * BINS + bin0 + bL) * FRAMES + fbase + fL]
                = qs[fL][bL];
        }
    }
    __syncthreads();
    for (int s2 = 128; s2; s2 >>= 1) {
        if (t < s2) rsum[t] += rsum[t + s2];
        __syncthreads();
    }
    if (t == 0) atomicAdd(&g_loss, rsum[0]);
}

// ---------------- finalize loss --------------------------------------------
__global__ void fin_k(float* __restrict__ out, int lossIdx) {
    if (threadIdx.x == 0)
        out[lossIdx] = 1.25f * g_loss / (float)((size_t)NTOT * BINS);
}

// ---------------- launch ----------------------------------------------------
extern "C" void kernel_launch(void* const* d_in, const int* in_sizes, int n_in,
                              void* d_out, int out_size)
{
    const float* x  = (const float*)d_in[0];
    const float* w1 = (const float*)d_in[1];
    const float* b1 = (const float*)d_in[2];
    const float* w2 = (const float*)d_in[3];
    const float* b2 = (const float*)d_in[4];
    const float* ws = (const float*)d_in[5];
    const float* bs = (const float*)d_in[6];
    const float* cb = (const float*)d_in[7];
    float* out = (float*)d_out;

    static bool attr_set = false;
    if (!attr_set) {
        cudaFuncSetAttribute(gemm_argmin_k,
                             cudaFuncAttributeMaxDynamicSharedMemorySize,
                             GEMM_SMEM_BYTES);
        attr_set = true;
    }

    init_k<<<((Cc * NTOT) + 255) / 256, 256>>>();
    conv_k<<<dim3(BINS / BT, FRAMES / FT, Bq), 256>>>(x, w1, b1, w2, b2, ws, bs);
    e2_k<<<(Cc * Ee) / 8, 256>>>(cb);
    gemm_argmin_k<<<dim3(Ee / BE, NTOT / BM, Cc), 256, GEMM_SMEM_BYTES>>>();
    gather_k<<<dim3(BINS / 32, NTOT / 32, Cc), 256>>>(cb, out);
    fin_k<<<1, 32>>>(out, out_size - 1);
}

// round 7
// speedup vs baseline: 1.7117x; 1.5230x over previous
#include <cuda_runtime.h>
#include <cstdint>

#define Bq      8
#define CIN     2
#define BINS    1024
#define FRAMES  512
#define Cc      8
#define Ee      1024
#define NTOT    (Bq * FRAMES)      // 4096 vectors per codebook channel

// ---------------- scratch (device globals: no allocation allowed) ----------
__device__ __align__(256) float g_v [(size_t)Cc * NTOT * BINS];  // v[c][n][bin]
__device__ __align__(256) float g_vh[(size_t)Cc * NTOT * BINS];  // tf32(v)
__device__ __align__(256) float g_cbh[(size_t)Cc * Ee * BINS];   // tf32(cb)
__device__ __align__(256) float g_d [(size_t)Cc * NTOT * Ee];    // approx scores
__device__ __align__(256) float g_e2[Cc * Ee];
__device__ int   g_emax[Cc];                                     // max e2 bits
__device__ __align__(256) unsigned long long g_arg[Cc * NTOT];
__device__ float g_loss;

__device__ __forceinline__ float tf32r(float x) {
    uint32_t h;
    asm("cvt.rna.tf32.f32 %0, %1;" : "=r"(h) : "f"(x));
    return __uint_as_float(h);
}

// ---------------- init ------------------------------------------------------
__global__ void init_k() {
    int i = blockIdx.x * blockDim.x + threadIdx.x;
    if (i == 0) g_loss = 0.0f;
    if (i < Cc) g_emax[i] = 0;
}

// ---------------- fused conv1 -> leaky -> conv2 + skip -> v (+tf32) --------
#define BT 16
#define FT 32

__global__ __launch_bounds__(256) void conv_k(
    const float* __restrict__ x,
    const float* __restrict__ w1, const float* __restrict__ b1,
    const float* __restrict__ w2, const float* __restrict__ b2,
    const float* __restrict__ ws, const float* __restrict__ bs)
{
    __shared__ float xs[CIN][BT + 16][FT + 1];
    __shared__ float h1s[Cc][BT + 8][FT + 1];
    __shared__ float w1s[Cc * CIN * 9];
    __shared__ float w2s[Cc * Cc * 9];
    __shared__ float wss[Cc * CIN];
    __shared__ float b1sh[Cc], b2sh[Cc], bssh[Cc];

    const int t    = threadIdx.x;
    const int bin0 = blockIdx.x * BT;
    const int f0   = blockIdx.y * FT;
    const int b    = blockIdx.z;

    for (int i = t; i < Cc * CIN * 9; i += 256) w1s[i] = w1[i];
    for (int i = t; i < Cc * Cc * 9;  i += 256) w2s[i] = w2[i];
    if (t < Cc * CIN) wss[t] = ws[t];
    if (t < Cc) { b1sh[t] = b1[t]; b2sh[t] = b2[t]; bssh[t] = bs[t]; }

    for (int p = t; p < CIN * (BT + 16) * FT; p += 256) {
        int f  = p % FT;
        int rb = (p / FT) % (BT + 16);
        int ci = p / (FT * (BT + 16));
        int gb = bin0 - 8 + rb;
        float v = 0.0f;
        if (gb >= 0 && gb < BINS)
            v = x[((size_t)(b * CIN + ci) * BINS + gb) * FRAMES + f0 + f];
        xs[ci][rb][f] = v;
    }
    __syncthreads();

    for (int p = t; p < (BT + 8) * FT; p += 256) {
        int f  = p % FT;
        int rb = p / FT;
        int gb = bin0 - 4 + rb;
        float acc[Cc];
#pragma unroll
        for (int c = 0; c < Cc; c++) acc[c] = b1sh[c];
#pragma unroll
        for (int ci = 0; ci < CIN; ci++)
#pragma unroll
            for (int k = 0; k < 9; k++) {
                float xv = xs[ci][rb + k][f];
#pragma unroll
                for (int c = 0; c < Cc; c++)
                    acc[c] += xv * w1s[(c * CIN + ci) * 9 + k];
            }
#pragma unroll
        for (int c = 0; c < Cc; c++) {
            float h = acc[c];
            h = (h >= 0.0f) ? h : 0.2f * h;
            if (gb < 0 || gb >= BINS) h = 0.0f;
            h1s[c][rb][f] = h;
        }
    }
    __syncthreads();

    const int binL = t % BT;
    const int fL0  = t / BT;
    float acc[2][Cc];
#pragma unroll
    for (int i = 0; i < 2; i++)
#pragma unroll
        for (int c = 0; c < Cc; c++) acc[i][c] = b2sh[c] + bssh[c];

#pragma unroll
    for (int c2 = 0; c2 < Cc; c2++)
#pragma unroll
        for (int k = 0; k < 9; k++) {
            float w[Cc];
#pragma unroll
            for (int c = 0; c < Cc; c++) w[c] = w2s[(c * Cc + c2) * 9 + k];
#pragma unroll
            for (int i = 0; i < 2; i++) {
                float hv = h1s[c2][binL + k][fL0 + 16 * i];
#pragma unroll
                for (int c = 0; c < Cc; c++) acc[i][c] += hv * w[c];
            }
        }
#pragma unroll
    for (int ci = 0; ci < CIN; ci++)
#pragma unroll
        for (int i = 0; i < 2; i++) {
            float xv = xs[ci][binL + 8][fL0 + 16 * i];
#pragma unroll
            for (int c = 0; c < Cc; c++) acc[i][c] += xv * wss[c * CIN + ci];
        }

    const int gb = bin0 + binL;
#pragma unroll
    for (int i = 0; i < 2; i++) {
        int n = b * FRAMES + f0 + fL0 + 16 * i;
#pragma unroll
        for (int c = 0; c < Cc; c++) {
            size_t idx = ((size_t)c * NTOT + n) * BINS + gb;
            float vv = acc[i][c];
            g_v[idx]  = vv;
            g_vh[idx] = tf32r(vv);
        }
    }
}

// ---------------- e2 + tf32(cb) + per-channel max e2 ------------------------
__global__ void e2_k(const float* __restrict__ cb) {
    int warp = threadIdx.x >> 5, lane = threadIdx.x & 31;
    int row  = blockIdx.x * 8 + warp;              // 0..8191
    const size_t base = (size_t)row * BINS;
    float s = 0.0f;
    for (int j = lane; j < BINS; j += 32) {
        float v = cb[base + j];
        s += v * v;
        g_cbh[base + j] = tf32r(v);
    }
#pragma unroll
    for (int o = 16; o; o >>= 1) s += __shfl_down_sync(0xffffffffu, s, o);
    if (lane == 0) {
        g_e2[row] = s;
        atomicMax(&g_emax[row / Ee], __float_as_int(s));   // s >= 0
    }
}

// ---------------- 1-pass tf32 tensor GEMM -> approx scores ------------------
// 128x128 tile, 8 warps (2m x 4n) of 64x32, BK=16 double-buffered cp.async.
#define BM   128
#define BE   128
#define BKs  16
#define STR  20
#define TILE_F (128 * STR)        // 2560 floats
#define BUF_F  (2 * TILE_F)       // A,B per buffer
#define GEMM_SMEM_BYTES (2 * BUF_F * 4)   // 40960

__device__ __forceinline__ void cp16(uint32_t dst, const float* src) {
    asm volatile("cp.async.cg.shared.global [%0], [%1], 16;" :: "r"(dst), "l"(src));
}

#define MMA_TF32(d, a, b) \
    asm volatile("mma.sync.aligned.m16n8k8.row.col.f32.tf32.tf32.f32 " \
                 "{%0,%1,%2,%3}, {%4,%5,%6,%7}, {%8,%9}, {%0,%1,%2,%3};" \
                 : "+f"(d[0]), "+f"(d[1]), "+f"(d[2]), "+f"(d[3]) \
                 : "r"(a[0]), "r"(a[1]), "r"(a[2]), "r"(a[3]), \
                   "r"(b[0]), "r"(b[1]))

__global__ __launch_bounds__(256, 2) void gemm_k() {
    extern __shared__ float S[];
    __shared__ float e2s[BE];

    const int t    = threadIdx.x;
    const int lane = t & 31;
    const int w    = t >> 5;
    const int m_base = (w >> 2) * 64;
    const int n_base = (w & 3) * 32;

    const int c     = blockIdx.z;
    const int eBase = blockIdx.x * BE;
    const int mBase = blockIdx.y * BM;

    const float* srcA = g_vh  + (size_t)c * NTOT * BINS + (size_t)mBase * BINS;
    const float* srcB = g_cbh + (size_t)c * Ee   * BINS + (size_t)eBase * BINS;

    const uint32_t sbase = (uint32_t)__cvta_generic_to_shared(S);

    auto load_slab = [&](int k0, int buf) {
#pragma unroll
        for (int i = 0; i < 2; i++) {
            int id  = t + 256 * i;
            int row = id >> 2;
            int kq  = (id & 3) * 4;
            cp16(sbase + (uint32_t)((buf * BUF_F + row * STR + kq) * 4),
                 srcA + (size_t)row * BINS + k0 + kq);
            cp16(sbase + (uint32_t)((buf * BUF_F + TILE_F + row * STR + kq) * 4),
                 srcB + (size_t)row * BINS + k0 + kq);
        }
        asm volatile("cp.async.commit_group;");
    };

    float acc[4][4][4];
#pragma unroll
    for (int mi = 0; mi < 4; mi++)
#pragma unroll
        for (int ni = 0; ni < 4; ni++)
#pragma unroll
            for (int r = 0; r < 4; r++) acc[mi][ni][r] = 0.0f;

    load_slab(0, 0);
    if (t < BE) e2s[t] = g_e2[c * Ee + eBase + t];

    const int r4 = lane >> 2;
    const int c4 = lane & 3;

    for (int s = 0; s < BINS / BKs; s++) {
        const int buf = s & 1;
        asm volatile("cp.async.wait_group 0;");
        __syncthreads();
        if (s + 1 < BINS / BKs) load_slab((s + 1) * BKs, buf ^ 1);

        const float* Ah = S + buf * BUF_F;
        const float* Bh = Ah + TILE_F;

#pragma unroll
        for (int ks = 0; ks < BKs; ks += 8) {
            uint32_t aH[4][4], bH[4][2];
#pragma unroll
            for (int mi = 0; mi < 4; mi++) {
                int o = (m_base + mi * 16 + r4) * STR + ks + c4;
                aH[mi][0] = __float_as_uint(Ah[o]);
                aH[mi][1] = __float_as_uint(Ah[o + 8 * STR]);
                aH[mi][2] = __float_as_uint(Ah[o + 4]);
                aH[mi][3] = __float_as_uint(Ah[o + 8 * STR + 4]);
            }
#pragma unroll
            for (int ni = 0; ni < 4; ni++) {
                int o = (n_base + ni * 8 + r4) * STR + ks + c4;
                bH[ni][0] = __float_as_uint(Bh[o]);
                bH[ni][1] = __float_as_uint(Bh[o + 4]);
            }
#pragma unroll
            for (int mi = 0; mi < 4; mi++)
#pragma unroll
                for (int ni = 0; ni < 4; ni++)
                    MMA_TF32(acc[mi][ni], aH[mi], bH[ni]);
        }
        __syncthreads();
    }

    // epilogue: write approx scores e2 - 2*dot
#pragma unroll
    for (int mi = 0; mi < 4; mi++)
#pragma unroll
        for (int h = 0; h < 2; h++) {
            int grow = mBase + m_base + mi * 16 + r4 + h * 8;
            float* dr = g_d + ((size_t)c * NTOT + grow) * Ee + eBase;
#pragma unroll
            for (int ni = 0; ni < 4; ni++) {
                int cl = n_base + ni * 8 + c4 * 2;
                float2 o2;
                o2.x = e2s[cl]     - 2.0f * acc[mi][ni][h * 2 + 0];
                o2.y = e2s[cl + 1] - 2.0f * acc[mi][ni][h * 2 + 1];
                *(float2*)(dr + cl) = o2;
            }
        }
}

// ---------------- select: certified argmin via candidate rescore ------------
__global__ __launch_bounds__(256) void select_k(const float* __restrict__ cb) {
    __shared__ float svr[BINS];
    __shared__ float sred[256];
    __shared__ int   scand[Ee];
    __shared__ int   scnt;
    __shared__ float sthr;

    const int t = threadIdx.x;
    const int n = blockIdx.x;
    const int c = blockIdx.y;
    const size_t row = (size_t)c * NTOT + n;

    // load scores (registers) + v row (smem) in one pass
    float4 s4 = ((const float4*)(g_d + row * Ee))[t];
    float4 v4 = ((const float4*)(g_v + row * BINS))[t];
    ((float4*)svr)[t] = v4;

    float lmin = fminf(fminf(s4.x, s4.y), fminf(s4.z, s4.w));
    sred[t] = lmin;
    __syncthreads();
    for (int s = 128; s; s >>= 1) {
        if (t < s) sred[t] = fminf(sred[t], sred[t + s]);
        __syncthreads();
    }
    const float minv = sred[0];
    __syncthreads();

    sred[t] = v4.x * v4.x + v4.y * v4.y + v4.z * v4.z + v4.w * v4.w;
    __syncthreads();
    for (int s = 128; s; s >>= 1) {
        if (t < s) sred[t] += sred[t + s];
        __syncthreads();
    }
    if (t == 0) {
        float vnorm = sqrtf(sred[0]);
        float emax  = sqrtf(__int_as_float(g_emax[c]));
        float delta = 0.002f * vnorm * emax + 0.1f;   // >= 2^-9*||v||*||e|| + slack
        sthr = minv + 2.0f * delta;
        scnt = 0;
    }
    __syncthreads();
    const float thr = sthr;

    if (s4.x <= thr) { int p = atomicAdd(&scnt, 1); scand[p] = t * 4 + 0; }
    if (s4.y <= thr) { int p = atomicAdd(&scnt, 1); scand[p] = t * 4 + 1; }
    if (s4.z <= thr) { int p = atomicAdd(&scnt, 1); scand[p] = t * 4 + 2; }
    if (s4.w <= thr) { int p = atomicAdd(&scnt, 1); scand[p] = t * 4 + 3; }
    __syncthreads();
    const int cnt = scnt;

    float best = 3.4e38f;
    int   bidx = 0x7fffffff;
    for (int ci = 0; ci < cnt; ci++) {
        const int e = scand[ci];
        float4 cbv = ((const float4*)(cb + ((size_t)c * Ee + e) * BINS))[t];
        float4 vv  = ((const float4*)svr)[t];
        float p = vv.x * cbv.x + vv.y * cbv.y + vv.z * cbv.z + vv.w * cbv.w;
#pragma unroll
        for (int o = 16; o; o >>= 1) p += __shfl_down_sync(0xffffffffu, p, o);
        if ((t & 31) == 0) sred[t >> 5] = p;
        __syncthreads();
        if (t == 0) {
            float dot = 0.0f;
#pragma unroll
            for (int wj = 0; wj < 8; wj++) dot += sred[wj];
            float sc = g_e2[c * Ee + e] - 2.0f * dot;
            if (sc < best || (sc == best && e < bidx)) { best = sc; bidx = e; }
        }
        __syncthreads();
    }
    if (t == 0) g_arg[row] = (unsigned long long)(unsigned)bidx;
}

// ---------------- gather + transpose + channel-reverse + loss --------------
__global__ __launch_bounds__(256) void gather_k(const float* __restrict__ cb,
                                                float* __restrict__ out)
{
    __shared__ float qs[32][33];
    __shared__ int   idxs[32];
    __shared__ float rsum[256];

    const int t    = threadIdx.x;
    const int c    = blockIdx.z;
    const int n0   = blockIdx.y * 32;
    const int bin0 = blockIdx.x * 32;

    if (t < 32) idxs[t] = (int)(g_arg[c * NTOT + n0 + t] & 0xFFFFFFFFULL);
    __syncthreads();

    {
        int binL = t % 32, fL0 = t / 32;
        float lacc = 0.0f;
#pragma unroll
        for (int i = 0; i < 4; i++) {
            int fL = fL0 + 8 * i;
            int n  = n0 + fL;
            float qv = cb[((size_t)c * Ee + idxs[fL]) * BINS + bin0 + binL];
            float vv = g_v[((size_t)c * NTOT + n) * BINS + bin0 + binL];
            float d = qv - vv;
            lacc += d * d;
            qs[fL][binL] = qv;
        }
        rsum[t] = lacc;
    }
    __syncthreads();

    {
        int fL = t % 32, bL0 = t / 32;
        int b = n0 / FRAMES, fbase = n0 % FRAMES;
        int cOut = (Cc - 1) - c;
#pragma unroll
        for (int i = 0; i < 4; i++) {
            int bL = bL0 + 8 * i;
            out[(((size_t)b * Cc + cOut) * BINS + bin0 + bL) * FRAMES + fbase + fL]
                = qs[fL][bL];
        }
    }
    __syncthreads();
    for (int s2 = 128; s2; s2 >>= 1) {
        if (t < s2) rsum[t] += rsum[t + s2];
        __syncthreads();
    }
    if (t == 0) atomicAdd(&g_loss, rsum[0]);
}

// ---------------- finalize loss --------------------------------------------
__global__ void fin_k(float* __restrict__ out, int lossIdx) {
    if (threadIdx.x == 0)
        out[lossIdx] = 1.25f * g_loss / (float)((size_t)NTOT * BINS);
}

// ---------------- launch ----------------------------------------------------
extern "C" void kernel_launch(void* const* d_in, const int* in_sizes, int n_in,
                              void* d_out, int out_size)
{
    const float* x  = (const float*)d_in[0];
    const float* w1 = (const float*)d_in[1];
    const float* b1 = (const float*)d_in[2];
    const float* w2 = (const float*)d_in[3];
    const float* b2 = (const float*)d_in[4];
    const float* ws = (const float*)d_in[5];
    const float* bs = (const float*)d_in[6];
    const float* cb = (const float*)d_in[7];
    float* out = (float*)d_out;

    init_k<<<1, 256>>>();
    conv_k<<<dim3(BINS / BT, FRAMES / FT, Bq), 256>>>(x, w1, b1, w2, b2, ws, bs);
    e2_k<<<(Cc * Ee) / 8, 256>>>(cb);
    gemm_k<<<dim3(Ee / BE, NTOT / BM, Cc), 256, GEMM_SMEM_BYTES>>>();
    select_k<<<dim3(NTOT, Cc), 256>>>(cb);
    gather_k<<<dim3(BINS / 32, NTOT / 32, Cc), 256>>>(cb, out);
    fin_k<<<1, 32>>>(out, out_size - 1);
}

// round 10
// speedup vs baseline: 2.3990x; 1.4015x over previous
#include <cuda_runtime.h>
#include <cuda_fp16.h>
#include <cstdint>

#define Bq      8
#define CIN     2
#define BINS    1024
#define FRAMES  512
#define Cc      8
#define Ee      1024
#define NTOT    (Bq * FRAMES)      // 4096 vectors per codebook channel

// ---------------- scratch (device globals: no allocation allowed) ----------
__device__ __align__(256) float  g_v [(size_t)Cc * NTOT * BINS]; // v[c][n][bin]
__device__ __align__(256) __half g_vh[(size_t)Cc * NTOT * BINS]; // fp16(v)
__device__ __align__(256) __half g_cbh[(size_t)Cc * Ee * BINS];  // fp16(cb)
__device__ __align__(256) float  g_d [(size_t)Cc * NTOT * Ee];   // approx scores
__device__ __align__(256) float  g_e2[Cc * Ee];
__device__ int   g_emax[Cc];                                     // max e2 bits
__device__ __align__(256) unsigned long long g_arg[Cc * NTOT];
__device__ float g_loss;

// ---------------- init ------------------------------------------------------
__global__ void init_k() {
    int i = blockIdx.x * blockDim.x + threadIdx.x;
    if (i == 0) g_loss = 0.0f;
    if (i < Cc) g_emax[i] = 0;
}

// ---------------- fused conv1 -> leaky -> conv2 + skip -> v (+fp16) --------
#define BT 16
#define FT 32

__global__ __launch_bounds__(256) void conv_k(
    const float* __restrict__ x,
    const float* __restrict__ w1, const float* __restrict__ b1,
    const float* __restrict__ w2, const float* __restrict__ b2,
    const float* __restrict__ ws, const float* __restrict__ bs)
{
    __shared__ float xs[CIN][BT + 16][FT + 1];
    __shared__ float h1s[Cc][BT + 8][FT + 1];
    __shared__ float w1s[Cc * CIN * 9];
    __shared__ float w2s[Cc * Cc * 9];
    __shared__ float wss[Cc * CIN];
    __shared__ float b1sh[Cc], b2sh[Cc], bssh[Cc];

    const int t    = threadIdx.x;
    const int bin0 = blockIdx.x * BT;
    const int f0   = blockIdx.y * FT;
    const int b    = blockIdx.z;

    for (int i = t; i < Cc * CIN * 9; i += 256) w1s[i] = w1[i];
    for (int i = t; i < Cc * Cc * 9;  i += 256) w2s[i] = w2[i];
    if (t < Cc * CIN) wss[t] = ws[t];
    if (t < Cc) { b1sh[t] = b1[t]; b2sh[t] = b2[t]; bssh[t] = bs[t]; }

    for (int p = t; p < CIN * (BT + 16) * FT; p += 256) {
        int f  = p % FT;
        int rb = (p / FT) % (BT + 16);
        int ci = p / (FT * (BT + 16));
        int gb = bin0 - 8 + rb;
        float v = 0.0f;
        if (gb >= 0 && gb < BINS)
            v = x[((size_t)(b * CIN + ci) * BINS + gb) * FRAMES + f0 + f];
        xs[ci][rb][f] = v;
    }
    __syncthreads();

    for (int p = t; p < (BT + 8) * FT; p += 256) {
        int f  = p % FT;
        int rb = p / FT;
        int gb = bin0 - 4 + rb;
        float acc[Cc];
#pragma unroll
        for (int c = 0; c < Cc; c++) acc[c] = b1sh[c];
#pragma unroll
        for (int ci = 0; ci < CIN; ci++)
#pragma unroll
            for (int k = 0; k < 9; k++) {
                float xv = xs[ci][rb + k][f];
#pragma unroll
                for (int c = 0; c < Cc; c++)
                    acc[c] += xv * w1s[(c * CIN + ci) * 9 + k];
            }
#pragma unroll
        for (int c = 0; c < Cc; c++) {
            float h = acc[c];
            h = (h >= 0.0f) ? h : 0.2f * h;
            if (gb < 0 || gb >= BINS) h = 0.0f;
            h1s[c][rb][f] = h;
        }
    }
    __syncthreads();

    const int binL = t % BT;
    const int fL0  = t / BT;
    float acc[2][Cc];
#pragma unroll
    for (int i = 0; i < 2; i++)
#pragma unroll
        for (int c = 0; c < Cc; c++) acc[i][c] = b2sh[c] + bssh[c];

#pragma unroll
    for (int c2 = 0; c2 < Cc; c2++)
#pragma unroll
        for (int k = 0; k < 9; k++) {
            float w[Cc];
#pragma unroll
            for (int c = 0; c < Cc; c++) w[c] = w2s[(c * Cc + c2) * 9 + k];
#pragma unroll
            for (int i = 0; i < 2; i++) {
                float hv = h1s[c2][binL + k][fL0 + 16 * i];
#pragma unroll
                for (int c = 0; c < Cc; c++) acc[i][c] += hv * w[c];
            }
        }
#pragma unroll
    for (int ci = 0; ci < CIN; ci++)
#pragma unroll
        for (int i = 0; i < 2; i++) {
            float xv = xs[ci][binL + 8][fL0 + 16 * i];
#pragma unroll
            for (int c = 0; c < Cc; c++) acc[i][c] += xv * wss[c * CIN + ci];
        }

    const int gb = bin0 + binL;
#pragma unroll
    for (int i = 0; i < 2; i++) {
        int n = b * FRAMES + f0 + fL0 + 16 * i;
#pragma unroll
        for (int c = 0; c < Cc; c++) {
            size_t idx = ((size_t)c * NTOT + n) * BINS + gb;
            float vv = acc[i][c];
            g_v[idx]  = vv;
            g_vh[idx] = __float2half(vv);   // round-to-nearest
        }
    }
}

// ---------------- e2 + fp16(cb) + per-channel max e2 ------------------------
__global__ void e2_k(const float* __restrict__ cb) {
    int warp = threadIdx.x >> 5, lane = threadIdx.x & 31;
    int row  = blockIdx.x * 8 + warp;              // 0..8191
    const size_t base = (size_t)row * BINS;
    float s = 0.0f;
    for (int j = lane; j < BINS; j += 32) {
        float v = cb[base + j];
        s += v * v;
        g_cbh[base + j] = __float2half(v);
    }
#pragma unroll
    for (int o = 16; o; o >>= 1) s += __shfl_down_sync(0xffffffffu, s, o);
    if (lane == 0) {
        g_e2[row] = s;
        atomicMax(&g_emax[row / Ee], __float_as_int(s));   // s >= 0
    }
}

// ---------------- 1-pass fp16 tensor GEMM -> approx scores ------------------
// 128x128 tile, 8 warps (2m x 4n) of 64x32, BK=64 halves (128B rows, SW128
// swizzle), double-buffered cp.async, m16n8k16.f32.f16.f16.f32.
#define BM   128
#define BE   128
#define BKh  64                       // halves per slab = 128 bytes
#define MATB 16384                    // 128 rows * 128 B
#define BUFB (2 * MATB)               // A + B per buffer
#define GEMM_SMEM_BYTES (2 * BUFB)    // 65536

__device__ __forceinline__ void cp16(uint32_t dst, const void* src) {
    asm volatile("cp.async.cg.shared.global [%0], [%1], 16;" :: "r"(dst), "l"(src));
}

// half2 fragment load with SW128 swizzle: row has 64 halves = 8 x 16B chunks,
// chunk' = chunk ^ (row & 7). p = half index within row (even).
__device__ __forceinline__ uint32_t ld_h2(const char* base, int row, int p) {
    int col = p * 2;                                 // byte column 0..127
    int sw  = ((col >> 4) ^ (row & 7)) << 4 | (col & 15);
    return *(const uint32_t*)(base + row * 128 + sw);
}

#define MMA_F16(d, a, b) \
    asm volatile("mma.sync.aligned.m16n8k16.row.col.f32.f16.f16.f32 " \
                 "{%0,%1,%2,%3}, {%4,%5,%6,%7}, {%8,%9}, {%0,%1,%2,%3};" \
                 : "+f"(d[0]), "+f"(d[1]), "+f"(d[2]), "+f"(d[3]) \
                 : "r"(a[0]), "r"(a[1]), "r"(a[2]), "r"(a[3]), \
                   "r"(b[0]), "r"(b[1]))

__global__ __launch_bounds__(256, 2) void gemm_k() {
    extern __shared__ __align__(128) char S[];
    __shared__ float e2s[BE];

    const int t    = threadIdx.x;
    const int lane = t & 31;
    const int w    = t >> 5;
    const int m_base = (w >> 2) * 64;
    const int n_base = (w & 3) * 32;

    const int c     = blockIdx.z;
    const int eBase = blockIdx.x * BE;
    const int mBase = blockIdx.y * BM;

    const __half* srcA = g_vh  + (size_t)c * NTOT * BINS + (size_t)mBase * BINS;
    const __half* srcB = g_cbh + (size_t)c * Ee   * BINS + (size_t)eBase * BINS;

    const uint32_t sbase = (uint32_t)__cvta_generic_to_shared(S);

    // slab loader: 2 matrices x 128 rows x 8 chunks = 2048 cp16 / 256 thr = 8
    auto load_slab = [&](int k0, int buf) {
#pragma unroll
        for (int i = 0; i < 8; i++) {
            int id  = t + 256 * i;
            int m   = id >> 10;              // 0..1
            int cid = id & 1023;
            int row = cid >> 3;
            int q   = cid & 7;
            const __half* src = (m == 0 ? srcA : srcB) + (size_t)row * BINS + k0 + q * 8;
            cp16(sbase + (uint32_t)(buf * BUFB + m * MATB + row * 128
                                    + ((q ^ (row & 7)) << 4)),
                 src);
        }
        asm volatile("cp.async.commit_group;");
    };

    float acc[4][4][4];
#pragma unroll
    for (int mi = 0; mi < 4; mi++)
#pragma unroll
        for (int ni = 0; ni < 4; ni++)
#pragma unroll
            for (int r = 0; r < 4; r++) acc[mi][ni][r] = 0.0f;

    load_slab(0, 0);
    if (t < BE) e2s[t] = g_e2[c * Ee + eBase + t];

    const int r4 = lane >> 2;     // group id 0..7
    const int c4 = lane & 3;      // thread-in-group 0..3

    for (int s = 0; s < BINS / BKh; s++) {
        const int buf = s & 1;
        asm volatile("cp.async.wait_group 0;");
        __syncthreads();
        if (s + 1 < BINS / BKh) load_slab((s + 1) * BKh, buf ^ 1);

        const char* Ah = S + buf * BUFB;
        const char* Bh = Ah + MATB;

#pragma unroll
        for (int ks = 0; ks < BKh; ks += 16) {
            uint32_t aF[4][4], bF[4][2];
#pragma unroll
            for (int mi = 0; mi < 4; mi++) {
                int row = m_base + mi * 16 + r4;
                int p   = ks + c4 * 2;
                aF[mi][0] = ld_h2(Ah, row,     p);
                aF[mi][1] = ld_h2(Ah, row + 8, p);
                aF[mi][2] = ld_h2(Ah, row,     p + 8);
                aF[mi][3] = ld_h2(Ah, row + 8, p + 8);
            }
#pragma unroll
            for (int ni = 0; ni < 4; ni++) {
                int row = n_base + ni * 8 + r4;
                int p   = ks + c4 * 2;
                bF[ni][0] = ld_h2(Bh, row, p);
                bF[ni][1] = ld_h2(Bh, row, p + 8);
            }
#pragma unroll
            for (int mi = 0; mi < 4; mi++)
#pragma unroll
                for (int ni = 0; ni < 4; ni++)
                    MMA_F16(acc[mi][ni], aF[mi], bF[ni]);
        }
        __syncthreads();
    }

    // epilogue: write approx scores e2 - 2*dot
#pragma unroll
    for (int mi = 0; mi < 4; mi++)
#pragma unroll
        for (int h = 0; h < 2; h++) {
            int grow = mBase + m_base + mi * 16 + r4 + h * 8;
            float* dr = g_d + ((size_t)c * NTOT + grow) * Ee + eBase;
#pragma unroll
            for (int ni = 0; ni < 4; ni++) {
                int cl = n_base + ni * 8 + c4 * 2;
                float2 o2;
                o2.x = e2s[cl]     - 2.0f * acc[mi][ni][h * 2 + 0];
                o2.y = e2s[cl + 1] - 2.0f * acc[mi][ni][h * 2 + 1];
                *(float2*)(dr + cl) = o2;
            }
        }
}

// ---------------- select: certified argmin via candidate rescore ------------
__global__ __launch_bounds__(256) void select_k(const float* __restrict__ cb) {
    __shared__ float svr[BINS];
    __shared__ float sred[256];
    __shared__ int   scand[Ee];
    __shared__ int   scnt;
    __shared__ float sthr;

    const int t = threadIdx.x;
    const int n = blockIdx.x;
    const int c = blockIdx.y;
    const size_t row = (size_t)c * NTOT + n;

    float4 s4 = ((const float4*)(g_d + row * Ee))[t];
    float4 v4 = ((const float4*)(g_v + row * BINS))[t];
    ((float4*)svr)[t] = v4;

    float lmin = fminf(fminf(s4.x, s4.y), fminf(s4.z, s4.w));
    sred[t] = lmin;
    __syncthreads();
    for (int s = 128; s; s >>= 1) {
        if (t < s) sred[t] = fminf(sred[t], sred[t + s]);
        __syncthreads();
    }
    const float minv = sred[0];
    __syncthreads();

    sred[t] = v4.x * v4.x + v4.y * v4.y + v4.z * v4.z + v4.w * v4.w;
    __syncthreads();
    for (int s = 128; s; s >>= 1) {
        if (t < s) sred[t] += sred[t + s];
        __syncthreads();
    }
    if (t == 0) {
        float vnorm = sqrtf(sred[0]);
        float emax  = sqrtf(__int_as_float(g_emax[c]));
        float delta = 0.002f * vnorm * emax + 0.1f;   // >= 2^-9*||v||*||e|| + slack
        sthr = minv + 2.0f * delta;
        scnt = 0;
    }
    __syncthreads();
    const float thr = sthr;

    if (s4.x <= thr) { int p = atomicAdd(&scnt, 1); scand[p] = t * 4 + 0; }
    if (s4.y <= thr) { int p = atomicAdd(&scnt, 1); scand[p] = t * 4 + 1; }
    if (s4.z <= thr) { int p = atomicAdd(&scnt, 1); scand[p] = t * 4 + 2; }
    if (s4.w <= thr) { int p = atomicAdd(&scnt, 1); scand[p] = t * 4 + 3; }
    __syncthreads();
    const int cnt = scnt;

    // sole candidate must be the true argmin (certified window)
    if (cnt == 1) {
        if (t == 0) g_arg[row] = (unsigned long long)(unsigned)scand[0];
        return;
    }

    float best = 3.4e38f;
    int   bidx = 0x7fffffff;
    for (int ci = 0; ci < cnt; ci++) {
        const int e = scand[ci];
        float4 cbv = ((const float4*)(cb + ((size_t)c * Ee + e) * BINS))[t];
        float4 vv  = ((const float4*)svr)[t];
        float p = vv.x * cbv.x + vv.y * cbv.y + vv.z * cbv.z + vv.w * cbv.w;
#pragma unroll
        for (int o = 16; o; o >>= 1) p += __shfl_down_sync(0xffffffffu, p, o);
        if ((t & 31) == 0) sred[t >> 5] = p;
        __syncthreads();
        if (t == 0) {
            float dot = 0.0f;
#pragma unroll
            for (int wj = 0; wj < 8; wj++) dot += sred[wj];
            float sc = g_e2[c * Ee + e] - 2.0f * dot;
            if (sc < best || (sc == best && e < bidx)) { best = sc; bidx = e; }
        }
        __syncthreads();
    }
    if (t == 0) g_arg[row] = (unsigned long long)(unsigned)bidx;
}

// ---------------- gather + transpose + channel-reverse + loss --------------
__global__ __launch_bounds__(256) void gather_k(const float* __restrict__ cb,
                                                float* __restrict__ out)
{
    __shared__ float qs[32][33];
    __shared__ int   idxs[32];
    __shared__ float rsum[256];

    const int t    = threadIdx.x;
    const int c    = blockIdx.z;
    const int n0   = blockIdx.y * 32;
    const int bin0 = blockIdx.x * 32;

    if (t < 32) idxs[t] = (int)(g_arg[c * NTOT + n0 + t] & 0xFFFFFFFFULL);
    __syncthreads();

    {
        int binL = t % 32, fL0 = t / 32;
        float lacc = 0.0f;
#pragma unroll
        for (int i = 0; i < 4; i++) {
            int fL = fL0 + 8 * i;
            int n  = n0 + fL;
            float qv = cb[((size_t)c * Ee + idxs[fL]) * BINS + bin0 + binL];
            float vv = g_v[((size_t)c * NTOT + n) * BINS + bin0 + binL];
            float d = qv - vv;
            lacc += d * d;
            qs[fL][binL] = qv;
        }
        rsum[t] = lacc;
    }
    __syncthreads();

    {
        int fL = t % 32, bL0 = t / 32;
        int b = n0 / FRAMES, fbase = n0 % FRAMES;
        int cOut = (Cc - 1) - c;
#pragma unroll
        for (int i = 0; i < 4; i++) {
            int bL = bL0 + 8 * i;
            out[(((size_t)b * Cc + cOut) * BINS + bin0 + bL) * FRAMES + fbase + fL]
                = qs[fL][bL];
        }
    }
    __syncthreads();
    for (int s2 = 128; s2; s2 >>= 1) {
        if (t < s2) rsum[t] += rsum[t + s2];
        __syncthreads();
    }
    if (t == 0) atomicAdd(&g_loss, rsum[0]);
}

// ---------------- finalize loss --------------------------------------------
__global__ void fin_k(float* __restrict__ out, int lossIdx) {
    if (threadIdx.x == 0)
        out[lossIdx] = 1.25f * g_loss / (float)((size_t)NTOT * BINS);
}

// ---------------- launch ----------------------------------------------------
extern "C" void kernel_launch(void* const* d_in, const int* in_sizes, int n_in,
                              void* d_out, int out_size)
{
    const float* x  = (const float*)d_in[0];
    const float* w1 = (const float*)d_in[1];
    const float* b1 = (const float*)d_in[2];
    const float* w2 = (const float*)d_in[3];
    const float* b2 = (const float*)d_in[4];
    const float* ws = (const float*)d_in[5];
    const float* bs = (const float*)d_in[6];
    const float* cb = (const float*)d_in[7];
    float* out = (float*)d_out;

    cudaFuncSetAttribute(gemm_k,
                         cudaFuncAttributeMaxDynamicSharedMemorySize,
                         GEMM_SMEM_BYTES);

    init_k<<<1, 256>>>();
    conv_k<<<dim3(BINS / BT, FRAMES / FT, Bq), 256>>>(x, w1, b1, w2, b2, ws, bs);
    e2_k<<<(Cc * Ee) / 8, 256>>>(cb);
    gemm_k<<<dim3(Ee / BE, NTOT / BM, Cc), 256, GEMM_SMEM_BYTES>>>();
    select_k<<<dim3(NTOT, Cc), 256>>>(cb);
    gather_k<<<dim3(BINS / 32, NTOT / 32, Cc), 256>>>(cb, out);
    fin_k<<<1, 32>>>(out, out_size - 1);
}

// round 11
// speedup vs baseline: 2.5436x; 1.0603x over previous
#include <cuda_runtime.h>
#include <cuda_fp16.h>
#include <cstdint>

#define Bq      8
#define CIN     2
#define BINS    1024
#define FRAMES  512
#define Cc      8
#define Ee      1024
#define NTOT    (Bq * FRAMES)      // 4096 vectors per codebook channel

// ---------------- scratch (device globals: no allocation allowed) ----------
__device__ __align__(256) float  g_v [(size_t)Cc * NTOT * BINS]; // v[c][n][bin]
__device__ __align__(256) __half g_vh[(size_t)Cc * NTOT * BINS]; // fp16(v)
__device__ __align__(256) __half g_cbh[(size_t)Cc * Ee * BINS];  // fp16(cb)
__device__ __align__(256) float  g_d [(size_t)Cc * NTOT * Ee];   // approx scores
__device__ __align__(256) float  g_e2[Cc * Ee];
__device__ __align__(256) float  g_vn2[Cc * NTOT];               // row norms^2
__device__ int   g_emax[Cc];                                     // max e2 bits
__device__ __align__(256) unsigned long long g_arg[Cc * NTOT];
__device__ float g_loss;

// ---------------- init ------------------------------------------------------
__global__ void init_k() {
    int i = blockIdx.x * blockDim.x + threadIdx.x;
    if (i == 0) g_loss = 0.0f;
    if (i < Cc) g_emax[i] = 0;
}

// ---------------- fused conv1 -> leaky -> conv2 + skip -> v (+fp16) --------
#define BT 16
#define FT 32

__global__ __launch_bounds__(256) void conv_k(
    const float* __restrict__ x,
    const float* __restrict__ w1, const float* __restrict__ b1,
    const float* __restrict__ w2, const float* __restrict__ b2,
    const float* __restrict__ ws, const float* __restrict__ bs)
{
    __shared__ float xs[CIN][BT + 16][FT + 1];
    __shared__ float h1s[Cc][BT + 8][FT + 1];
    __shared__ float w1s[Cc * CIN * 9];
    __shared__ float w2s[Cc * Cc * 9];
    __shared__ float wss[Cc * CIN];
    __shared__ float b1sh[Cc], b2sh[Cc], bssh[Cc];

    const int t    = threadIdx.x;
    const int bin0 = blockIdx.x * BT;
    const int f0   = blockIdx.y * FT;
    const int b    = blockIdx.z;

    for (int i = t; i < Cc * CIN * 9; i += 256) w1s[i] = w1[i];
    for (int i = t; i < Cc * Cc * 9;  i += 256) w2s[i] = w2[i];
    if (t < Cc * CIN) wss[t] = ws[t];
    if (t < Cc) { b1sh[t] = b1[t]; b2sh[t] = b2[t]; bssh[t] = bs[t]; }

    for (int p = t; p < CIN * (BT + 16) * FT; p += 256) {
        int f  = p % FT;
        int rb = (p / FT) % (BT + 16);
        int ci = p / (FT * (BT + 16));
        int gb = bin0 - 8 + rb;
        float v = 0.0f;
        if (gb >= 0 && gb < BINS)
            v = x[((size_t)(b * CIN + ci) * BINS + gb) * FRAMES + f0 + f];
        xs[ci][rb][f] = v;
    }
    __syncthreads();

    for (int p = t; p < (BT + 8) * FT; p += 256) {
        int f  = p % FT;
        int rb = p / FT;
        int gb = bin0 - 4 + rb;
        float acc[Cc];
#pragma unroll
        for (int c = 0; c < Cc; c++) acc[c] = b1sh[c];
#pragma unroll
        for (int ci = 0; ci < CIN; ci++)
#pragma unroll
            for (int k = 0; k < 9; k++) {
                float xv = xs[ci][rb + k][f];
#pragma unroll
                for (int c = 0; c < Cc; c++)
                    acc[c] += xv * w1s[(c * CIN + ci) * 9 + k];
            }
#pragma unroll
        for (int c = 0; c < Cc; c++) {
            float h = acc[c];
            h = (h >= 0.0f) ? h : 0.2f * h;
            if (gb < 0 || gb >= BINS) h = 0.0f;
            h1s[c][rb][f] = h;
        }
    }
    __syncthreads();

    const int binL = t % BT;
    const int fL0  = t / BT;
    float acc[2][Cc];
#pragma unroll
    for (int i = 0; i < 2; i++)
#pragma unroll
        for (int c = 0; c < Cc; c++) acc[i][c] = b2sh[c] + bssh[c];

#pragma unroll
    for (int c2 = 0; c2 < Cc; c2++)
#pragma unroll
        for (int k = 0; k < 9; k++) {
            float w[Cc];
#pragma unroll
            for (int c = 0; c < Cc; c++) w[c] = w2s[(c * Cc + c2) * 9 + k];
#pragma unroll
            for (int i = 0; i < 2; i++) {
                float hv = h1s[c2][binL + k][fL0 + 16 * i];
#pragma unroll
                for (int c = 0; c < Cc; c++) acc[i][c] += hv * w[c];
            }
        }
#pragma unroll
    for (int ci = 0; ci < CIN; ci++)
#pragma unroll
        for (int i = 0; i < 2; i++) {
            float xv = xs[ci][binL + 8][fL0 + 16 * i];
#pragma unroll
            for (int c = 0; c < Cc; c++) acc[i][c] += xv * wss[c * CIN + ci];
        }

    const int gb = bin0 + binL;
#pragma unroll
    for (int i = 0; i < 2; i++) {
        int n = b * FRAMES + f0 + fL0 + 16 * i;
#pragma unroll
        for (int c = 0; c < Cc; c++) {
            size_t idx = ((size_t)c * NTOT + n) * BINS + gb;
            float vv = acc[i][c];
            g_v[idx]  = vv;
            g_vh[idx] = __float2half(vv);   // round-to-nearest
        }
    }
}

// ---------------- e2 + fp16(cb) + per-channel max e2 ------------------------
__global__ void e2_k(const float* __restrict__ cb) {
    int warp = threadIdx.x >> 5, lane = threadIdx.x & 31;
    int row  = blockIdx.x * 8 + warp;              // 0..8191
    const size_t base = (size_t)row * BINS;
    float s = 0.0f;
    for (int j = lane; j < BINS; j += 32) {
        float v = cb[base + j];
        s += v * v;
        g_cbh[base + j] = __float2half(v);
    }
#pragma unroll
    for (int o = 16; o; o >>= 1) s += __shfl_down_sync(0xffffffffu, s, o);
    if (lane == 0) {
        g_e2[row] = s;
        atomicMax(&g_emax[row / Ee], __float_as_int(s));   // s >= 0
    }
}

// ---------------- vn2 = ||v row||^2 -----------------------------------------
__global__ void vn2_k() {
    int warp = threadIdx.x >> 5, lane = threadIdx.x & 31;
    int row  = blockIdx.x * 8 + warp;              // 0..32767
    const float4* p = (const float4*)(g_v + (size_t)row * BINS);
    float s = 0.0f;
#pragma unroll
    for (int j = 0; j < 8; j++) {
        float4 v = p[lane + 32 * j];
        s += v.x * v.x + v.y * v.y + v.z * v.z + v.w * v.w;
    }
#pragma unroll
    for (int o = 16; o; o >>= 1) s += __shfl_down_sync(0xffffffffu, s, o);
    if (lane == 0) g_vn2[row] = s;
}

// ---------------- 1-pass fp16 tensor GEMM -> approx scores ------------------
// 128x128 tile, 8 warps (2m x 4n) of 64x32, BK=64 halves (128B rows, SW128
// swizzle), double-buffered cp.async, ldmatrix fragments, m16n8k16.
#define BM   128
#define BE   128
#define BKh  64                       // halves per slab = 128 bytes
#define MATB 16384                    // 128 rows * 128 B
#define BUFB (2 * MATB)               // A + B per buffer
#define GEMM_SMEM_BYTES (2 * BUFB)    // 65536

__device__ __forceinline__ void cp16(uint32_t dst, const void* src) {
    asm volatile("cp.async.cg.shared.global [%0], [%1], 16;" :: "r"(dst), "l"(src));
}

__device__ __forceinline__ void ldsm_x4(uint32_t a, uint32_t& r0, uint32_t& r1,
                                        uint32_t& r2, uint32_t& r3) {
    asm volatile("ldmatrix.sync.aligned.m8n8.x4.shared.b16 {%0,%1,%2,%3}, [%4];"
                 : "=r"(r0), "=r"(r1), "=r"(r2), "=r"(r3) : "r"(a));
}
__device__ __forceinline__ void ldsm_x2(uint32_t a, uint32_t& r0, uint32_t& r1) {
    asm volatile("ldmatrix.sync.aligned.m8n8.x2.shared.b16 {%0,%1}, [%2];"
                 : "=r"(r0), "=r"(r1) : "r"(a));
}

#define MMA_F16(d, a, b) \
    asm volatile("mma.sync.aligned.m16n8k16.row.col.f32.f16.f16.f32 " \
                 "{%0,%1,%2,%3}, {%4,%5,%6,%7}, {%8,%9}, {%0,%1,%2,%3};" \
                 : "+f"(d[0]), "+f"(d[1]), "+f"(d[2]), "+f"(d[3]) \
                 : "r"(a[0]), "r"(a[1]), "r"(a[2]), "r"(a[3]), \
                   "r"(b[0]), "r"(b[1]))

__global__ __launch_bounds__(256, 2) void gemm_k() {
    extern __shared__ __align__(128) char S[];
    __shared__ float e2s[BE];

    const int t    = threadIdx.x;
    const int lane = t & 31;
    const int w    = t >> 5;
    const int m_base = (w >> 2) * 64;
    const int n_base = (w & 3) * 32;

    const int c     = blockIdx.z;
    const int eBase = blockIdx.x * BE;
    const int mBase = blockIdx.y * BM;

    const __half* srcA = g_vh  + (size_t)c * NTOT * BINS + (size_t)mBase * BINS;
    const __half* srcB = g_cbh + (size_t)c * Ee   * BINS + (size_t)eBase * BINS;

    const uint32_t sbase = (uint32_t)__cvta_generic_to_shared(S);

    auto load_slab = [&](int k0, int buf) {
#pragma unroll
        for (int i = 0; i < 8; i++) {
            int id  = t + 256 * i;
            int m   = id >> 10;              // 0..1
            int cid = id & 1023;
            int row = cid >> 3;
            int q   = cid & 7;
            const __half* src = (m == 0 ? srcA : srcB) + (size_t)row * BINS + k0 + q * 8;
            cp16(sbase + (uint32_t)(buf * BUFB + m * MATB + row * 128
                                    + ((q ^ (row & 7)) << 4)),
                 src);
        }
        asm volatile("cp.async.commit_group;");
    };

    float acc[4][4][4];
#pragma unroll
    for (int mi = 0; mi < 4; mi++)
#pragma unroll
        for (int ni = 0; ni < 4; ni++)
#pragma unroll
            for (int r = 0; r < 4; r++) acc[mi][ni][r] = 0.0f;

    load_slab(0, 0);
    if (t < BE) e2s[t] = g_e2[c * Ee + eBase + t];

    // ldmatrix lane roles
    const int amat = lane >> 3;          // 0..3
    const int arow = lane & 7;
    const int a_row_off = ((amat & 1) << 3) + arow;  // +0/+8 within 16-row frag
    const int a_ck_off  = amat >> 1;                 // +0/+1 chunk (k+8)
    const int b_ck_off  = amat & 1;                  // lanes 0-7:+0, 8-15:+1

    for (int s = 0; s < BINS / BKh; s++) {
        const int buf = s & 1;
        asm volatile("cp.async.wait_group 0;");
        __syncthreads();
        if (s + 1 < BINS / BKh) load_slab((s + 1) * BKh, buf ^ 1);

        const uint32_t Ah = sbase + buf * BUFB;
        const uint32_t Bh = Ah + MATB;

#pragma unroll
        for (int ks = 0; ks < BKh; ks += 16) {
            const int cks = ks >> 3;       // chunk base 0,2,4,6
            uint32_t aF[4][4], bF[4][2];
#pragma unroll
            for (int mi = 0; mi < 4; mi++) {
                int row = m_base + mi * 16 + a_row_off;
                int ch  = cks + a_ck_off;
                ldsm_x4(Ah + row * 128 + ((ch ^ (row & 7)) << 4),
                        aF[mi][0], aF[mi][1], aF[mi][2], aF[mi][3]);
            }
#pragma unroll
            for (int ni = 0; ni < 4; ni++) {
                int row = n_base + ni * 8 + arow;
                int ch  = cks + b_ck_off;
                ldsm_x2(Bh + row * 128 + ((ch ^ (row & 7)) << 4),
                        bF[ni][0], bF[ni][1]);
            }
#pragma unroll
            for (int mi = 0; mi < 4; mi++)
#pragma unroll
                for (int ni = 0; ni < 4; ni++)
                    MMA_F16(acc[mi][ni], aF[mi], bF[ni]);
        }
        __syncthreads();
    }

    // epilogue: write approx scores e2 - 2*dot
    const int r4 = lane >> 2;
    const int c4 = lane & 3;
#pragma unroll
    for (int mi = 0; mi < 4; mi++)
#pragma unroll
        for (int h = 0; h < 2; h++) {
            int grow = mBase + m_base + mi * 16 + r4 + h * 8;
            float* dr = g_d + ((size_t)c * NTOT + grow) * Ee + eBase;
#pragma unroll
            for (int ni = 0; ni < 4; ni++) {
                int cl = n_base + ni * 8 + c4 * 2;
                float2 o2;
                o2.x = e2s[cl]     - 2.0f * acc[mi][ni][h * 2 + 0];
                o2.y = e2s[cl + 1] - 2.0f * acc[mi][ni][h * 2 + 1];
                *(float2*)(dr + cl) = o2;
            }
        }
}

// ---------------- select: certified argmin, warp per row --------------------
#define CAND_CAP 128

__global__ __launch_bounds__(256) void select_k(const float* __restrict__ cb) {
    __shared__ int scand[8][CAND_CAP];
    __shared__ int scnt[8];

    const int t    = threadIdx.x;
    const int lane = t & 31;
    const int wp   = t >> 5;
    const int n    = blockIdx.x * 8 + wp;
    const int c    = blockIdx.y;
    const size_t row = (size_t)c * NTOT + n;

    const float4* dr = (const float4*)(g_d + row * Ee);
    float4 sc[8];
    float lmin = 3.4e38f;
#pragma unroll
    for (int j = 0; j < 8; j++) {
        sc[j] = dr[lane + 32 * j];
        lmin = fminf(lmin, fminf(fminf(sc[j].x, sc[j].y), fminf(sc[j].z, sc[j].w)));
    }
#pragma unroll
    for (int o = 16; o; o >>= 1)
        lmin = fminf(lmin, __shfl_xor_sync(0xffffffffu, lmin, o));

    const float delta = 0.002f * sqrtf(g_vn2[row])
                               * sqrtf(__int_as_float(g_emax[c])) + 0.1f;
    const float thr = lmin + 2.0f * delta;

    int cntL = 0, idxL = 0x7fffffff;
#pragma unroll
    for (int j = 0; j < 8; j++) {
        int base = 4 * (lane + 32 * j);
        if (sc[j].x <= thr) { cntL++; idxL = min(idxL, base + 0); }
        if (sc[j].y <= thr) { cntL++; idxL = min(idxL, base + 1); }
        if (sc[j].z <= thr) { cntL++; idxL = min(idxL, base + 2); }
        if (sc[j].w <= thr) { cntL++; idxL = min(idxL, base + 3); }
    }
    int cnt = cntL, idxm = idxL;
#pragma unroll
    for (int o = 16; o; o >>= 1) {
        cnt  += __shfl_xor_sync(0xffffffffu, cnt, o);
        idxm  = min(idxm, __shfl_xor_sync(0xffffffffu, idxm, o));
    }

    if (cnt == 1) {            // sole candidate in certified window = argmin
        if (lane == 0) g_arg[row] = (unsigned long long)(unsigned)idxm;
        return;
    }

    // gather candidate list (order-independent final pick)
    if (lane == 0) scnt[wp] = 0;
    __syncwarp();
    bool full_scan = (cnt > CAND_CAP);
    if (!full_scan) {
#pragma unroll
        for (int j = 0; j < 8; j++) {
            int base = 4 * (lane + 32 * j);
            if (sc[j].x <= thr) scand[wp][atomicAdd(&scnt[wp], 1)] = base + 0;
            if (sc[j].y <= thr) scand[wp][atomicAdd(&scnt[wp], 1)] = base + 1;
            if (sc[j].z <= thr) scand[wp][atomicAdd(&scnt[wp], 1)] = base + 2;
            if (sc[j].w <= thr) scand[wp][atomicAdd(&scnt[wp], 1)] = base + 3;
        }
    }
    __syncwarp();

    // exact fp32 rescore of candidates
    const float4* vr = (const float4*)(g_v + row * BINS);
    float4 v[8];
#pragma unroll
    for (int j = 0; j < 8; j++) v[j] = vr[lane + 32 * j];

    float best = 3.4e38f;
    int   bidx = 0x7fffffff;
    const int total = full_scan ? Ee : cnt;
    for (int ci = 0; ci < total; ci++) {
        const int e = full_scan ? ci : scand[wp][ci];
        const float4* cr = (const float4*)(cb + ((size_t)c * Ee + e) * BINS);
        float p = 0.0f;
#pragma unroll
        for (int j = 0; j < 8; j++) {
            float4 cv = cr[lane + 32 * j];
            p += v[j].x * cv.x + v[j].y * cv.y + v[j].z * cv.z + v[j].w * cv.w;
        }
#pragma unroll
        for (int o = 16; o; o >>= 1)
            p += __shfl_xor_sync(0xffffffffu, p, o);
        float s = g_e2[c * Ee + e] - 2.0f * p;     // same on all lanes
        if (s < best || (s == best && e < bidx)) { best = s; bidx = e; }
    }
    if (lane == 0) g_arg[row] = (unsigned long long)(unsigned)bidx;
}

// ---------------- gather + transpose + channel-reverse + loss --------------
__global__ __launch_bounds__(256) void gather_k(const float* __restrict__ cb,
                                                float* __restrict__ out)
{
    __shared__ float qs[32][33];
    __shared__ int   idxs[32];
    __shared__ float rsum[256];

    const int t    = threadIdx.x;
    const int c    = blockIdx.z;
    const int n0   = blockIdx.y * 32;
    const int bin0 = blockIdx.x * 32;

    if (t < 32) idxs[t] = (int)(g_arg[c * NTOT + n0 + t] & 0xFFFFFFFFULL);
    __syncthreads();

    {
        int binL = t % 32, fL0 = t / 32;
        float lacc = 0.0f;
#pragma unroll
        for (int i = 0; i < 4; i++) {
            int fL = fL0 + 8 * i;
            int n  = n0 + fL;
            float qv = cb[((size_t)c * Ee + idxs[fL]) * BINS + bin0 + binL];
            float vv = g_v[((size_t)c * NTOT + n) * BINS + bin0 + binL];
            float d = qv - vv;
            lacc += d * d;
            qs[fL][binL] = qv;
        }
        rsum[t] = lacc;
    }
    __syncthreads();

    {
        int fL = t % 32, bL0 = t / 32;
        int b = n0 / FRAMES, fbase = n0 % FRAMES;
        int cOut = (Cc - 1) - c;
#pragma unroll
        for (int i = 0; i < 4; i++) {
            int bL = bL0 + 8 * i;
            out[(((size_t)b * Cc + cOut) * BINS + bin0 + bL) * FRAMES + fbase + fL]
                = qs[fL][bL];
        }
    }
    __syncthreads();
    for (int s2 = 128; s2; s2 >>= 1) {
        if (t < s2) rsum[t] += rsum[t + s2];
        __syncthreads();
    }
    if (t == 0) atomicAdd(&g_loss, rsum[0]);
}

// ---------------- finalize loss --------------------------------------------
__global__ void fin_k(float* __restrict__ out, int lossIdx) {
    if (threadIdx.x == 0)
        out[lossIdx] = 1.25f * g_loss / (float)((size_t)NTOT * BINS);
}

// ---------------- launch ----------------------------------------------------
extern "C" void kernel_launch(void* const* d_in, const int* in_sizes, int n_in,
                              void* d_out, int out_size)
{
    const float* x  = (const float*)d_in[0];
    const float* w1 = (const float*)d_in[1];
    const float* b1 = (const float*)d_in[2];
    const float* w2 = (const float*)d_in[3];
    const float* b2 = (const float*)d_in[4];
    const float* ws = (const float*)d_in[5];
    const float* bs = (const float*)d_in[6];
    const float* cb = (const float*)d_in[7];
    float* out = (float*)d_out;

    cudaFuncSetAttribute(gemm_k,
                         cudaFuncAttributeMaxDynamicSharedMemorySize,
                         GEMM_SMEM_BYTES);

    init_k<<<1, 256>>>();
    conv_k<<<dim3(BINS / BT, FRAMES / FT, Bq), 256>>>(x, w1, b1, w2, b2, ws, bs);
    e2_k<<<(Cc * Ee) / 8, 256>>>(cb);
    vn2_k<<<(Cc * NTOT) / 8, 256>>>();
    gemm_k<<<dim3(Ee / BE, NTOT / BM, Cc), 256, GEMM_SMEM_BYTES>>>();
    select_k<<<dim3(NTOT / 8, Cc), 256>>>(cb);
    gather_k<<<dim3(BINS / 32, NTOT / 32, Cc), 256>>>(cb, out);
    fin_k<<<1, 32>>>(out, out_size - 1);
}